// round 4
// baseline (speedup 1.0000x reference)
#include <cuda_runtime.h>
#include <cuda_bf16.h>
#include <math.h>

#define DM   2560
#define NH   32
#define HD   80
#define BSZ  32      // keys per block
#define NB   32      // number of key blocks
#define KTOP 16
#define BATCH 2
#define SEQ  1024
#define NTOK (BATCH*SEQ)          // 2048
#define ATT_SCALE 0.1118033988749895f  // 80^-0.5

// ---------------- scratch (device globals; no runtime allocation) ----------------
__device__ float g_q   [NTOK * DM];
__device__ float g_k   [NTOK * DM];
__device__ float g_v   [NTOK * DM];
__device__ float g_comb[NTOK * DM];
__device__ float g_gh  [NTOK * (DM/2)];
__device__ float g_gates[NTOK * 3];
__device__ float g_kbar[BATCH * NH * NB * HD];
__device__ float g_Acomp[BATCH * NH * NB * DM];   // 4096 x 2560
__device__ float g_H1   [BATCH * NH * NB * 320];  // 4096 x 320
__device__ float g_kc   [BATCH * NH * NB * HD];
__device__ float g_vc   [BATCH * NH * NB * HD];
__device__ unsigned g_sel[BATCH * NH * SEQ];

__device__ __forceinline__ float gelu_f(float x) {
    return 0.5f * x * (1.0f + erff(x * 0.70710678118654752f));
}

__device__ __forceinline__ void split_bf16(float x, unsigned short& h, unsigned short& l) {
    __nv_bfloat16 hb = __float2bfloat16_rn(x);
    __nv_bfloat16 lb = __float2bfloat16_rn(x - __bfloat162float(hb));
    h = __bfloat16_as_ushort(hb);
    l = __bfloat16_as_ushort(lb);
}

__device__ __forceinline__ void mma_bf16(float c[4], unsigned a0, unsigned a1,
                                         unsigned a2, unsigned a3,
                                         unsigned b0, unsigned b1) {
    asm volatile(
        "mma.sync.aligned.m16n8k16.row.col.f32.bf16.bf16.f32 "
        "{%0,%1,%2,%3}, {%4,%5,%6,%7}, {%8,%9}, {%0,%1,%2,%3};"
        : "+f"(c[0]), "+f"(c[1]), "+f"(c[2]), "+f"(c[3])
        : "r"(a0), "r"(a1), "r"(a2), "r"(a3), "r"(b0), "r"(b1));
}

// ============= Tensor-core GEMM (3-term bf16 split) — SMOOTH PATHS ONLY ==========
// C[M,N] = act(A[M,K] @ B[K,N] + bias). M%128==0, K%16==0. N tail guarded.
// 128x128 tile, BK=16, 256 thr = 8 warps (2m x 4n), warp tile 64x32.
// ~8e-6 relative error: OK for V/gate/comp/Wo (all feed smooth functions),
// NOT for Q/K (feed discrete top-k selection -> use fp32 sgemm there).
#define KS 24   // smem row stride (bf16 elems) -> conflict-free fragment loads
__global__ void __launch_bounds__(256) mma_gemm_kernel(
    const float* __restrict__ A, const float* __restrict__ B,
    const float* __restrict__ bias, float* __restrict__ C,
    int M, int N, int K, int act)
{
    __shared__ unsigned short AsH[2][128][KS];
    __shared__ unsigned short AsL[2][128][KS];
    __shared__ unsigned short BsH[2][128][KS];   // [n][k] (transposed on fill)
    __shared__ unsigned short BsL[2][128][KS];

    const int tid  = threadIdx.x;
    const int lane = tid & 31;
    const int w    = tid >> 5;
    const int warp_m = (w & 1) * 64;
    const int warp_n = (w >> 1) * 32;
    const int row0 = blockIdx.y * 128;
    const int col0 = blockIdx.x * 128;
    const int g  = lane >> 2;
    const int t4 = lane & 3;

    float acc[4][4][4];
#pragma unroll
    for (int mi = 0; mi < 4; mi++)
#pragma unroll
        for (int ni = 0; ni < 4; ni++)
#pragma unroll
            for (int c = 0; c < 4; c++) acc[mi][ni][c] = 0.f;

    const int ntiles = K / 16;
    float4 pa[2], pb[2];

    // ---- prefetch tile 0 into regs ----
#pragma unroll
    for (int i = 0; i < 2; i++) {
        int idx = tid * 2 + i;
        int ar = idx >> 2, ak4 = idx & 3;
        pa[i] = *(const float4*)&A[(row0 + ar) * K + ak4 * 4];
        int bidx = tid + 256 * i;
        int bk = bidx >> 5, bn4 = bidx & 31;
        int c = col0 + bn4 * 4;
        if (c + 3 < N) pb[i] = *(const float4*)&B[bk * N + c];
        else {
            pb[i].x = (c + 0 < N) ? B[bk * N + c + 0] : 0.f;
            pb[i].y = (c + 1 < N) ? B[bk * N + c + 1] : 0.f;
            pb[i].z = (c + 2 < N) ? B[bk * N + c + 2] : 0.f;
            pb[i].w = (c + 3 < N) ? B[bk * N + c + 3] : 0.f;
        }
    }

    int buf = 0;
#pragma unroll
    for (int i = 0; i < 2; i++) {
        int idx = tid * 2 + i;
        int ar = idx >> 2, ak4 = idx & 3;
        float va[4] = {pa[i].x, pa[i].y, pa[i].z, pa[i].w};
#pragma unroll
        for (int j = 0; j < 4; j++) {
            unsigned short h, l; split_bf16(va[j], h, l);
            AsH[0][ar][ak4*4+j] = h; AsL[0][ar][ak4*4+j] = l;
        }
        int bidx = tid + 256 * i;
        int bk = bidx >> 5, bn4 = bidx & 31;
        float vb[4] = {pb[i].x, pb[i].y, pb[i].z, pb[i].w};
#pragma unroll
        for (int j = 0; j < 4; j++) {
            unsigned short bh, bl; split_bf16(vb[j], bh, bl);
            BsH[0][bn4*4+j][bk] = bh; BsL[0][bn4*4+j][bk] = bl;
        }
    }
    __syncthreads();

    for (int t = 0; t < ntiles; t++) {
        const bool more = (t + 1 < ntiles);
        if (more) {
            const int kt = (t + 1) * 16;
#pragma unroll
            for (int i = 0; i < 2; i++) {
                int idx = tid * 2 + i;
                int ar = idx >> 2, ak4 = idx & 3;
                pa[i] = *(const float4*)&A[(row0 + ar) * K + kt + ak4 * 4];
                int bidx = tid + 256 * i;
                int bk = bidx >> 5, bn4 = bidx & 31;
                int c = col0 + bn4 * 4;
                if (c + 3 < N) pb[i] = *(const float4*)&B[(kt + bk) * N + c];
                else {
                    pb[i].x = (c + 0 < N) ? B[(kt + bk) * N + c + 0] : 0.f;
                    pb[i].y = (c + 1 < N) ? B[(kt + bk) * N + c + 1] : 0.f;
                    pb[i].z = (c + 2 < N) ? B[(kt + bk) * N + c + 2] : 0.f;
                    pb[i].w = (c + 3 < N) ? B[(kt + bk) * N + c + 3] : 0.f;
                }
            }
        }

        unsigned aH[4][4], aL[4][4], bH[4][2], bL[4][2];
#pragma unroll
        for (int mi = 0; mi < 4; mi++) {
            const int r = warp_m + mi * 16 + g;
            aH[mi][0] = *(const unsigned*)&AsH[buf][r    ][2*t4];
            aH[mi][1] = *(const unsigned*)&AsH[buf][r + 8][2*t4];
            aH[mi][2] = *(const unsigned*)&AsH[buf][r    ][2*t4 + 8];
            aH[mi][3] = *(const unsigned*)&AsH[buf][r + 8][2*t4 + 8];
            aL[mi][0] = *(const unsigned*)&AsL[buf][r    ][2*t4];
            aL[mi][1] = *(const unsigned*)&AsL[buf][r + 8][2*t4];
            aL[mi][2] = *(const unsigned*)&AsL[buf][r    ][2*t4 + 8];
            aL[mi][3] = *(const unsigned*)&AsL[buf][r + 8][2*t4 + 8];
        }
#pragma unroll
        for (int ni = 0; ni < 4; ni++) {
            const int n = warp_n + ni * 8 + g;
            bH[ni][0] = *(const unsigned*)&BsH[buf][n][2*t4];
            bH[ni][1] = *(const unsigned*)&BsH[buf][n][2*t4 + 8];
            bL[ni][0] = *(const unsigned*)&BsL[buf][n][2*t4];
            bL[ni][1] = *(const unsigned*)&BsL[buf][n][2*t4 + 8];
        }

#pragma unroll
        for (int mi = 0; mi < 4; mi++)
#pragma unroll
            for (int ni = 0; ni < 4; ni++) {
                mma_bf16(acc[mi][ni], aH[mi][0], aH[mi][1], aH[mi][2], aH[mi][3],
                         bH[ni][0], bH[ni][1]);
                mma_bf16(acc[mi][ni], aH[mi][0], aH[mi][1], aH[mi][2], aH[mi][3],
                         bL[ni][0], bL[ni][1]);
                mma_bf16(acc[mi][ni], aL[mi][0], aL[mi][1], aL[mi][2], aL[mi][3],
                         bH[ni][0], bH[ni][1]);
            }

        if (more) {
            const int nb = buf ^ 1;
#pragma unroll
            for (int i = 0; i < 2; i++) {
                int idx = tid * 2 + i;
                int ar = idx >> 2, ak4 = idx & 3;
                float va[4] = {pa[i].x, pa[i].y, pa[i].z, pa[i].w};
#pragma unroll
                for (int j = 0; j < 4; j++) {
                    unsigned short h, l; split_bf16(va[j], h, l);
                    AsH[nb][ar][ak4*4+j] = h; AsL[nb][ar][ak4*4+j] = l;
                }
                int bidx = tid + 256 * i;
                int bk = bidx >> 5, bn4 = bidx & 31;
                float vb[4] = {pb[i].x, pb[i].y, pb[i].z, pb[i].w};
#pragma unroll
                for (int j = 0; j < 4; j++) {
                    unsigned short bh, bl; split_bf16(vb[j], bh, bl);
                    BsH[nb][bn4*4+j][bk] = bh; BsL[nb][bn4*4+j][bk] = bl;
                }
            }
            __syncthreads();
            buf = nb;
        }
    }

    // ---- epilogue ----
#pragma unroll
    for (int mi = 0; mi < 4; mi++) {
#pragma unroll
        for (int ni = 0; ni < 4; ni++) {
            const int row = row0 + warp_m + mi * 16 + g;
            const int col = col0 + warp_n + ni * 8 + 2 * t4;
            if (col + 1 < N) {
                float2 o0, o1;
                o0.x = acc[mi][ni][0] + bias[col];
                o0.y = acc[mi][ni][1] + bias[col + 1];
                o1.x = acc[mi][ni][2] + bias[col];
                o1.y = acc[mi][ni][3] + bias[col + 1];
                if (act == 1) {
                    o0.x = gelu_f(o0.x); o0.y = gelu_f(o0.y);
                    o1.x = gelu_f(o1.x); o1.y = gelu_f(o1.y);
                }
                *(float2*)&C[row * N + col]       = o0;
                *(float2*)&C[(row + 8) * N + col] = o1;
            } else if (col < N) {
                float v0 = acc[mi][ni][0] + bias[col];
                float v1 = acc[mi][ni][2] + bias[col];
                if (act == 1) { v0 = gelu_f(v0); v1 = gelu_f(v1); }
                C[row * N + col]       = v0;
                C[(row + 8) * N + col] = v1;
            }
        }
    }
}

// ------------- fp32 SGEMM — SELECTION-CRITICAL PATHS (Q, K) + tiny comp2 ---------
__global__ void __launch_bounds__(256, 2) sgemm_kernel(
    const float* __restrict__ A, const float* __restrict__ B,
    const float* __restrict__ bias, float* __restrict__ C,
    int M, int N, int K, int act)
{
    __shared__ float As[2][16][132];
    __shared__ float Bs[2][16][128];

    const int tid  = threadIdx.x;
    const int row0 = blockIdx.y * 128;
    const int col0 = blockIdx.x * 128;
    const int trow = (tid >> 4) * 8;
    const int tcol = (tid & 15) * 8;

    const int a_row = tid >> 2;
    const int a_k   = (tid & 3) * 4;
    const int b_k   = tid >> 5;
    const int b_col = (tid & 31) * 4;
    const int gcol  = col0 + b_col;
    const bool bok  = (gcol < N);

    float acc[8][8];
#pragma unroll
    for (int i = 0; i < 8; i++)
#pragma unroll
        for (int j = 0; j < 8; j++) acc[i][j] = 0.f;

    float4 aReg[2], bReg[2];
    const int ntiles = K / 16;

#pragma unroll
    for (int i = 0; i < 2; i++) {
        aReg[i] = *(const float4*)&A[(row0 + a_row + i * 64) * K + a_k];
        bReg[i] = bok ? *(const float4*)&B[(b_k + i * 8) * N + gcol]
                      : make_float4(0.f, 0.f, 0.f, 0.f);
    }
#pragma unroll
    for (int i = 0; i < 2; i++) {
        As[0][a_k + 0][a_row + i * 64] = aReg[i].x;
        As[0][a_k + 1][a_row + i * 64] = aReg[i].y;
        As[0][a_k + 2][a_row + i * 64] = aReg[i].z;
        As[0][a_k + 3][a_row + i * 64] = aReg[i].w;
        *(float4*)&Bs[0][b_k + i * 8][b_col] = bReg[i];
    }
    __syncthreads();

    int buf = 0;
    for (int t = 0; t < ntiles; t++) {
        if (t + 1 < ntiles) {
            const int koff = (t + 1) * 16;
#pragma unroll
            for (int i = 0; i < 2; i++) {
                aReg[i] = *(const float4*)&A[(row0 + a_row + i * 64) * K + koff + a_k];
                bReg[i] = bok ? *(const float4*)&B[(koff + b_k + i * 8) * N + gcol]
                              : make_float4(0.f, 0.f, 0.f, 0.f);
            }
        }
#pragma unroll
        for (int k = 0; k < 16; k++) {
            float ar[8], br[8];
            *(float4*)&ar[0] = *(const float4*)&As[buf][k][trow];
            *(float4*)&ar[4] = *(const float4*)&As[buf][k][trow + 4];
            *(float4*)&br[0] = *(const float4*)&Bs[buf][k][tcol];
            *(float4*)&br[4] = *(const float4*)&Bs[buf][k][tcol + 4];
#pragma unroll
            for (int i = 0; i < 8; i++)
#pragma unroll
                for (int j = 0; j < 8; j++) acc[i][j] += ar[i] * br[j];
        }
        if (t + 1 < ntiles) {
            const int nb = buf ^ 1;
#pragma unroll
            for (int i = 0; i < 2; i++) {
                As[nb][a_k + 0][a_row + i * 64] = aReg[i].x;
                As[nb][a_k + 1][a_row + i * 64] = aReg[i].y;
                As[nb][a_k + 2][a_row + i * 64] = aReg[i].z;
                As[nb][a_k + 3][a_row + i * 64] = aReg[i].w;
                *(float4*)&Bs[nb][b_k + i * 8][b_col] = bReg[i];
            }
            __syncthreads();
            buf = nb;
        }
    }

#pragma unroll
    for (int i = 0; i < 8; i++) {
        const int r = row0 + trow + i;
#pragma unroll
        for (int j = 0; j < 8; j++) {
            const int c = col0 + tcol + j;
            if (c < N) {
                float val = acc[i][j] + bias[c];
                if (act == 1) val = gelu_f(val);
                C[r * N + c] = val;
            }
        }
    }
}

// ---------------- block-mean keys ------------------------------------------------
__global__ void kbar_kernel(const float* __restrict__ k, float* __restrict__ kb)
{
    int idx = blockIdx.x * 256 + threadIdx.x;
    int d = idx % HD;
    int n = (idx / HD) & 31;
    int h = (idx / (HD * 32)) & 31;
    int b = idx / (HD * 32 * 32);
    float s = 0.f;
#pragma unroll
    for (int j = 0; j < 32; j++)
        s += k[(b * SEQ + n * BSZ + j) * DM + h * HD + d];
    kb[idx] = s * 0.03125f;
}

// ------------- gather for compression MLP ---------------------------------------
__global__ void gather_comp(const float* __restrict__ t, const float* __restrict__ pos,
                            float* __restrict__ A)
{
    int idx = blockIdx.x * 256 + threadIdx.x;
    int c = idx % DM;
    int row = idx / DM;
    int n = row & 31;
    int h = (row >> 5) & 31;
    int b = row >> 10;
    int j = c / HD, d = c - j * HD;
    A[idx] = t[(b * SEQ + n * BSZ + j) * DM + h * HD + d] + pos[c];
}

// ---------------- top-k block selection -------------------------------------------
__global__ void __launch_bounds__(64) topk_kernel(
    const float* __restrict__ q, const float* __restrict__ kbar,
    unsigned* __restrict__ sel)
{
    __shared__ float Qs[64][84];
    __shared__ float Kb[32][84];
    const int q0 = blockIdx.x * 64;
    const int h = blockIdx.y, b = blockIdx.z;
    const int tid = threadIdx.x;

    for (int idx = tid; idx < 64 * 20; idx += 64) {
        int row = idx / 20, d4 = idx - row * 20;
        *(float4*)&Qs[row][d4 * 4] =
            *(const float4*)&q[(b * SEQ + q0 + row) * DM + h * HD + d4 * 4];
    }
    for (int idx = tid; idx < 32 * 20; idx += 64) {
        int row = idx / 20, d4 = idx - row * 20;
        *(float4*)&Kb[row][d4 * 4] =
            *(const float4*)&kbar[((b * NH + h) * NB + row) * HD + d4 * 4];
    }
    __syncthreads();

    float sc[32];
#pragma unroll
    for (int n = 0; n < 32; n++) {
        float s = 0.f;
        for (int d4 = 0; d4 < 20; d4++) {
            float4 qv = *(const float4*)&Qs[tid][d4 * 4];
            float4 kv = *(const float4*)&Kb[n][d4 * 4];
            s += qv.x * kv.x + qv.y * kv.y + qv.z * kv.z + qv.w * kv.w;
        }
        sc[n] = s;
    }
    unsigned mask = 0;
#pragma unroll
    for (int t = 0; t < KTOP; t++) {
        float best = -1e38f; int bi = 0;
#pragma unroll
        for (int n = 0; n < 32; n++) {
            if (!((mask >> n) & 1u) && sc[n] > best) { best = sc[n]; bi = n; }
        }
        mask |= (1u << bi);
    }
    sel[(b * NH + h) * SEQ + q0 + tid] = mask;
}

// ---------------- gates ------------------------------------------------------------
__global__ void __launch_bounds__(256) gates_kernel(
    const float* __restrict__ gh, const float* __restrict__ W2,
    const float* __restrict__ b2, float* __restrict__ gates)
{
    int gw = (blockIdx.x * 256 + threadIdx.x) >> 5;
    int lane = threadIdx.x & 31;
    if (gw >= NTOK * 3) return;
    int row = gw / 3, col = gw - row * 3;
    float s = 0.f;
    for (int i = lane; i < DM / 2; i += 32)
        s += gh[row * (DM / 2) + i] * W2[i * 3 + col];
#pragma unroll
    for (int o = 16; o > 0; o >>= 1) s += __shfl_down_sync(0xffffffffu, s, o);
    if (lane == 0)
        gates[row * 3 + col] = 1.f / (1.f + __expf(-(s + b2[col])));
}

// ---------------- fused attention: window + selected + compressed ----------------
__global__ void __launch_bounds__(256) attn_kernel(
    const float* __restrict__ q, const float* __restrict__ k, const float* __restrict__ v,
    const float* __restrict__ kc, const float* __restrict__ vc,
    const unsigned* __restrict__ sel, const float* __restrict__ gates,
    float* __restrict__ comb)
{
    __shared__ float Qs[32][84];
    __shared__ float Ks[32][84];
    __shared__ float Vs[32][84];
    __shared__ float Ssm[32][36];

    const int q0 = blockIdx.x * 32;
    const int h  = blockIdx.y;
    const int b  = blockIdx.z;
    const int tid = threadIdx.x;
    const int qi = tid >> 3;
    const int r  = tid & 7;
    const int d0 = r * 10;
    const int j0 = r * 4;

    for (int idx = tid; idx < 32 * 20; idx += 256) {
        int row = idx / 20, d4 = idx - row * 20;
        *(float4*)&Qs[row][d4 * 4] =
            *(const float4*)&q[(b * SEQ + q0 + row) * DM + h * HD + d4 * 4];
    }
    const unsigned msel = sel[(b * NH + h) * SEQ + q0 + qi];
    const int qrow = b * SEQ + q0 + qi;

    float mrun = -1e30f, lw = 0.f, ls = 0.f;
    float aw[10], asv[10];
#pragma unroll
    for (int i = 0; i < 10; i++) { aw[i] = 0.f; asv[i] = 0.f; }

    for (int n = 0; n < NB; n++) {
        __syncthreads();
        for (int idx = tid; idx < 32 * 20; idx += 256) {
            int row = idx / 20, d4 = idx - row * 20;
            int g = (b * SEQ + n * BSZ + row) * DM + h * HD + d4 * 4;
            *(float4*)&Ks[row][d4 * 4] = *(const float4*)&k[g];
            *(float4*)&Vs[row][d4 * 4] = *(const float4*)&v[g];
        }
        __syncthreads();

        float s0 = 0.f, s1 = 0.f, s2 = 0.f, s3 = 0.f;
#pragma unroll
        for (int d4 = 0; d4 < 20; d4++) {
            float4 qv = *(const float4*)&Qs[qi][d4 * 4];
            float4 k0 = *(const float4*)&Ks[j0 + 0][d4 * 4];
            float4 k1 = *(const float4*)&Ks[j0 + 1][d4 * 4];
            float4 k2 = *(const float4*)&Ks[j0 + 2][d4 * 4];
            float4 k3 = *(const float4*)&Ks[j0 + 3][d4 * 4];
            s0 += qv.x * k0.x + qv.y * k0.y + qv.z * k0.z + qv.w * k0.w;
            s1 += qv.x * k1.x + qv.y * k1.y + qv.z * k1.z + qv.w * k1.w;
            s2 += qv.x * k2.x + qv.y * k2.y + qv.z * k2.z + qv.w * k2.w;
            s3 += qv.x * k3.x + qv.y * k3.y + qv.z * k3.z + qv.w * k3.w;
        }
        s0 *= ATT_SCALE; s1 *= ATT_SCALE; s2 *= ATT_SCALE; s3 *= ATT_SCALE;
        *(float4*)&Ssm[qi][j0] = make_float4(s0, s1, s2, s3);
        __syncwarp();
        float mb = -1e30f;
#pragma unroll
        for (int j4 = 0; j4 < 8; j4++) {
            float4 t4 = *(const float4*)&Ssm[qi][j4 * 4];
            mb = fmaxf(mb, fmaxf(fmaxf(t4.x, t4.y), fmaxf(t4.z, t4.w)));
        }
        float mnew = fmaxf(mrun, mb);
        float alpha = __expf(mrun - mnew);
        __syncwarp();
        *(float4*)&Ssm[qi][j0] = make_float4(__expf(s0 - mnew), __expf(s1 - mnew),
                                             __expf(s2 - mnew), __expf(s3 - mnew));
        __syncwarp();

        float ps = 0.f;
        const float fsel = ((msel >> n) & 1u) ? 1.f : 0.f;
        lw *= alpha; ls *= alpha;
#pragma unroll
        for (int i = 0; i < 10; i++) { aw[i] *= alpha; asv[i] *= alpha; }
#pragma unroll
        for (int j4 = 0; j4 < 8; j4++) {
            float4 p4 = *(const float4*)&Ssm[qi][j4 * 4];
            ps += p4.x + p4.y + p4.z + p4.w;
            float pj[4] = {p4.x, p4.y, p4.z, p4.w};
#pragma unroll
            for (int jj = 0; jj < 4; jj++) {
                const float p  = pj[jj];
                const float pf = p * fsel;
                const int   j  = j4 * 4 + jj;
#pragma unroll
                for (int i2 = 0; i2 < 5; i2++) {
                    float2 v2 = *(const float2*)&Vs[j][d0 + 2 * i2];
                    aw[2 * i2]      += p  * v2.x;
                    aw[2 * i2 + 1]  += p  * v2.y;
                    asv[2 * i2]     += pf * v2.x;
                    asv[2 * i2 + 1] += pf * v2.y;
                }
            }
        }
        lw += ps;
        ls += fsel * ps;
        mrun = mnew;
    }

    __syncthreads();
    for (int idx = tid; idx < 32 * 20; idx += 256) {
        int row = idx / 20, d4 = idx - row * 20;
        int g = ((b * NH + h) * NB + row) * HD + d4 * 4;
        *(float4*)&Ks[row][d4 * 4] = *(const float4*)&kc[g];
        *(float4*)&Vs[row][d4 * 4] = *(const float4*)&vc[g];
    }
    __syncthreads();
    float c0 = 0.f, c1 = 0.f, c2 = 0.f, c3 = 0.f;
#pragma unroll
    for (int d4 = 0; d4 < 20; d4++) {
        float4 qv = *(const float4*)&Qs[qi][d4 * 4];
        float4 k0 = *(const float4*)&Ks[j0 + 0][d4 * 4];
        float4 k1 = *(const float4*)&Ks[j0 + 1][d4 * 4];
        float4 k2 = *(const float4*)&Ks[j0 + 2][d4 * 4];
        float4 k3 = *(const float4*)&Ks[j0 + 3][d4 * 4];
        c0 += qv.x * k0.x + qv.y * k0.y + qv.z * k0.z + qv.w * k0.w;
        c1 += qv.x * k1.x + qv.y * k1.y + qv.z * k1.z + qv.w * k1.w;
        c2 += qv.x * k2.x + qv.y * k2.y + qv.z * k2.z + qv.w * k2.w;
        c3 += qv.x * k3.x + qv.y * k3.y + qv.z * k3.z + qv.w * k3.w;
    }
    c0 *= ATT_SCALE; c1 *= ATT_SCALE; c2 *= ATT_SCALE; c3 *= ATT_SCALE;
    *(float4*)&Ssm[qi][j0] = make_float4(c0, c1, c2, c3);
    __syncwarp();
    float mc = -1e30f;
#pragma unroll
    for (int j4 = 0; j4 < 8; j4++) {
        float4 t4 = *(const float4*)&Ssm[qi][j4 * 4];
        mc = fmaxf(mc, fmaxf(fmaxf(t4.x, t4.y), fmaxf(t4.z, t4.w)));
    }
    __syncwarp();
    *(float4*)&Ssm[qi][j0] = make_float4(__expf(c0 - mc), __expf(c1 - mc),
                                         __expf(c2 - mc), __expf(c3 - mc));
    __syncwarp();
    float lc = 0.f;
    float ac[10];
#pragma unroll
    for (int i = 0; i < 10; i++) ac[i] = 0.f;
#pragma unroll
    for (int j4 = 0; j4 < 8; j4++) {
        float4 p4 = *(const float4*)&Ssm[qi][j4 * 4];
        lc += p4.x + p4.y + p4.z + p4.w;
        float pj[4] = {p4.x, p4.y, p4.z, p4.w};
#pragma unroll
        for (int jj = 0; jj < 4; jj++) {
            const float p = pj[jj];
            const int   j = j4 * 4 + jj;
#pragma unroll
            for (int i2 = 0; i2 < 5; i2++) {
                float2 v2 = *(const float2*)&Vs[j][d0 + 2 * i2];
                ac[2 * i2]     += p * v2.x;
                ac[2 * i2 + 1] += p * v2.y;
            }
        }
    }

    const float gc = gates[qrow * 3 + 0];
    const float gs = gates[qrow * 3 + 1];
    const float gw = gates[qrow * 3 + 2];
    const float ic  = gc / lc;
    const float isf = gs / ls;
    const float iwf = gw / lw;
#pragma unroll
    for (int i = 0; i < 10; i++)
        comb[qrow * DM + h * HD + d0 + i] = ic * ac[i] + isf * asv[i] + iwf * aw[i];
}

// ---------------------------------- launch ---------------------------------------
static inline int ceil_div(int a, int b) { return (a + b - 1) / b; }

extern "C" void kernel_launch(void* const* d_in, const int* in_sizes, int n_in,
                              void* d_out, int out_size)
{
    const float* hs       = (const float*)d_in[0];
    const float* Wq       = (const float*)d_in[1];
    const float* bq       = (const float*)d_in[2];
    const float* Wk       = (const float*)d_in[3];
    const float* bk       = (const float*)d_in[4];
    const float* Wv       = (const float*)d_in[5];
    const float* bv       = (const float*)d_in[6];
    const float* Wo       = (const float*)d_in[7];
    const float* bo       = (const float*)d_in[8];
    const float* comp_pos = (const float*)d_in[9];
    const float* comp_W1  = (const float*)d_in[10];
    const float* comp_b1  = (const float*)d_in[11];
    const float* comp_W2  = (const float*)d_in[12];
    const float* comp_b2  = (const float*)d_in[13];
    const float* gate_W1  = (const float*)d_in[14];
    const float* gate_b1  = (const float*)d_in[15];
    const float* gate_W2  = (const float*)d_in[16];
    const float* gate_b2  = (const float*)d_in[17];
    float* out = (float*)d_out;

    float *q, *k, *v, *comb, *gh, *gates, *kbar, *Acomp, *H1, *kc, *vc;
    unsigned* selp;
    cudaGetSymbolAddress((void**)&q,     g_q);
    cudaGetSymbolAddress((void**)&k,     g_k);
    cudaGetSymbolAddress((void**)&v,     g_v);
    cudaGetSymbolAddress((void**)&comb,  g_comb);
    cudaGetSymbolAddress((void**)&gh,    g_gh);
    cudaGetSymbolAddress((void**)&gates, g_gates);
    cudaGetSymbolAddress((void**)&kbar,  g_kbar);
    cudaGetSymbolAddress((void**)&Acomp, g_Acomp);
    cudaGetSymbolAddress((void**)&H1,    g_H1);
    cudaGetSymbolAddress((void**)&kc,    g_kc);
    cudaGetSymbolAddress((void**)&vc,    g_vc);
    cudaGetSymbolAddress((void**)&selp,  g_sel);

    // Q, K projections: fp32 (selection-critical — feed discrete top-k)
    // V projection: split-bf16 tensor cores (smooth path)
    {
        dim3 grid(DM / 128, NTOK / 128);
        sgemm_kernel<<<grid, 256>>>(hs, Wq, bq, q, NTOK, DM, DM, 0);
        sgemm_kernel<<<grid, 256>>>(hs, Wk, bk, k, NTOK, DM, DM, 0);
        mma_gemm_kernel<<<grid, 256>>>(hs, Wv, bv, v, NTOK, DM, DM, 0);
    }
    // gate hidden + gates (smooth)
    {
        dim3 grid((DM / 2) / 128, NTOK / 128);
        mma_gemm_kernel<<<grid, 256>>>(hs, gate_W1, gate_b1, gh, NTOK, DM / 2, DM, 1);
        gates_kernel<<<ceil_div(NTOK * 3 * 32, 256), 256>>>(gh, gate_W2, gate_b2, gates);
    }
    // block-mean keys (fp32 k -> selection exact)
    kbar_kernel<<<(BATCH * NH * NB * HD) / 256, 256>>>(k, kbar);

    // compression MLP for K (smooth)
    {
        gather_comp<<<(BATCH * NH * NB * DM) / 256, 256>>>(k, comp_pos, Acomp);
        dim3 g1(ceil_div(320, 128), (BATCH * NH * NB) / 128);
        mma_gemm_kernel<<<g1, 256>>>(Acomp, comp_W1, comp_b1, H1, BATCH * NH * NB, 320, DM, 1);
        dim3 g2(1, (BATCH * NH * NB) / 128);
        sgemm_kernel<<<g2, 256>>>(H1, comp_W2, comp_b2, kc, BATCH * NH * NB, HD, 320, 0);
    }
    // compression MLP for V (smooth)
    {
        gather_comp<<<(BATCH * NH * NB * DM) / 256, 256>>>(v, comp_pos, Acomp);
        dim3 g1(ceil_div(320, 128), (BATCH * NH * NB) / 128);
        mma_gemm_kernel<<<g1, 256>>>(Acomp, comp_W1, comp_b1, H1, BATCH * NH * NB, 320, DM, 1);
        dim3 g2(1, (BATCH * NH * NB) / 128);
        sgemm_kernel<<<g2, 256>>>(H1, comp_W2, comp_b2, vc, BATCH * NH * NB, HD, 320, 0);
    }

    // top-k block selection (fp32 q, kbar)
    {
        dim3 grid(SEQ / 64, NH, BATCH);
        topk_kernel<<<grid, 64>>>(q, kbar, selp);
    }
    // fused attention (window + selected + compressed + gating)
    {
        dim3 grid(SEQ / 32, NH, BATCH);
        attn_kernel<<<grid, 256>>>(q, k, v, kc, vc, selp, gates, comb);
    }
    // output projection (smooth) — tensor cores
    {
        dim3 grid(DM / 128, NTOK / 128);
        mma_gemm_kernel<<<grid, 256>>>(comb, Wo, bo, out, NTOK, DM, DM, 0);
    }
}

// round 5
// speedup vs baseline: 1.2359x; 1.2359x over previous
#include <cuda_runtime.h>
#include <cuda_bf16.h>
#include <math.h>

#define DM   2560
#define NH   32
#define HD   80
#define BSZ  32      // keys per block
#define NB   32      // number of key blocks
#define KTOP 16
#define BATCH 2
#define SEQ  1024
#define NTOK (BATCH*SEQ)          // 2048
#define NCOMP (BATCH*NH*NB)       // 4096
#define ATT_SCALE 0.1118033988749895f  // 80^-0.5

// ---------------- scratch (device globals; no runtime allocation) ----------------
__device__ float g_q   [NTOK * DM];
__device__ float g_k   [NTOK * DM];
__device__ float g_v   [NTOK * DM];
__device__ float g_comb[NTOK * DM];
__device__ float g_gh  [NTOK * (DM/2)];
__device__ float g_gates[NTOK * 3];
__device__ float g_kbar[BATCH * NH * NB * HD];
__device__ float g_H1  [NCOMP * 320];
__device__ float g_kc  [NCOMP * HD];
__device__ float g_vc  [NCOMP * HD];
__device__ unsigned g_sel[BATCH * NH * SEQ];

// pre-split bf16 operands (hi/lo), stored as ushort
__device__ unsigned short g_hsH[NTOK * DM],  g_hsL[NTOK * DM];
__device__ unsigned short g_cbH[NTOK * DM],  g_cbL[NTOK * DM];
__device__ unsigned short g_acH[NCOMP * DM], g_acL[NCOMP * DM];
__device__ unsigned short g_WvTH[DM * DM],   g_WvTL[DM * DM];
__device__ unsigned short g_WoTH[DM * DM],   g_WoTL[DM * DM];
__device__ unsigned short g_gW1TH[(DM/2) * DM], g_gW1TL[(DM/2) * DM];
__device__ unsigned short g_cW1TH[320 * DM], g_cW1TL[320 * DM];

__device__ __forceinline__ float gelu_f(float x) {
    return 0.5f * x * (1.0f + erff(x * 0.70710678118654752f));
}

__device__ __forceinline__ void split_bf16(float x, unsigned short& h, unsigned short& l) {
    __nv_bfloat16 hb = __float2bfloat16_rn(x);
    __nv_bfloat16 lb = __float2bfloat16_rn(x - __bfloat162float(hb));
    h = __bfloat16_as_ushort(hb);
    l = __bfloat16_as_ushort(lb);
}

__device__ __forceinline__ void mma_bf16(float c[4], unsigned a0, unsigned a1,
                                         unsigned a2, unsigned a3,
                                         unsigned b0, unsigned b1) {
    asm volatile(
        "mma.sync.aligned.m16n8k16.row.col.f32.bf16.bf16.f32 "
        "{%0,%1,%2,%3}, {%4,%5,%6,%7}, {%8,%9}, {%0,%1,%2,%3};"
        : "+f"(c[0]), "+f"(c[1]), "+f"(c[2]), "+f"(c[3])
        : "r"(a0), "r"(a1), "r"(a2), "r"(a3), "r"(b0), "r"(b1));
}

// ---------------- converts: split fp32 -> bf16 hi/lo ------------------------------
__global__ void split_vec_kernel(const float* __restrict__ x,
                                 unsigned short* __restrict__ h,
                                 unsigned short* __restrict__ l, int n4)
{
    int i = blockIdx.x * 256 + threadIdx.x;
    if (i >= n4) return;
    float4 v = *(const float4*)&x[i * 4];
    unsigned short hh[4], ll[4];
    split_bf16(v.x, hh[0], ll[0]); split_bf16(v.y, hh[1], ll[1]);
    split_bf16(v.z, hh[2], ll[2]); split_bf16(v.w, hh[3], ll[3]);
    *(ushort4*)&h[i * 4] = make_ushort4(hh[0], hh[1], hh[2], hh[3]);
    *(ushort4*)&l[i * 4] = make_ushort4(ll[0], ll[1], ll[2], ll[3]);
}

// W [K][N] fp32 -> WT [N][K] bf16 hi/lo. K,N mult of 32. block 32x8.
__global__ void split_tr_kernel(const float* __restrict__ W,
                                unsigned short* __restrict__ TH,
                                unsigned short* __restrict__ TL, int K, int N)
{
    __shared__ float tile[32][33];
    const int n0 = blockIdx.x * 32, k0 = blockIdx.y * 32;
    const int tx = threadIdx.x, ty = threadIdx.y;
#pragma unroll
    for (int j = 0; j < 4; j++)
        tile[ty + j * 8][tx] = W[(k0 + ty + j * 8) * N + n0 + tx];
    __syncthreads();
#pragma unroll
    for (int j = 0; j < 4; j++) {
        float vv = tile[tx][ty + j * 8];
        unsigned short h, l; split_bf16(vv, h, l);
        TH[(n0 + ty + j * 8) * K + k0 + tx] = h;
        TL[(n0 + ty + j * 8) * K + k0 + tx] = l;
    }
}

// gather for compression MLP, emitting split bf16 directly
__global__ void gather_comp_split(const float* __restrict__ t, const float* __restrict__ pos,
                                  unsigned short* __restrict__ AH,
                                  unsigned short* __restrict__ AL)
{
    int idx = blockIdx.x * 256 + threadIdx.x;   // NCOMP*DM total
    int c = idx % DM;
    int row = idx / DM;                          // (b*32+h)*32+n
    int n = row & 31;
    int h = (row >> 5) & 31;
    int b = row >> 10;
    int j = c / HD, d = c - j * HD;
    float val = t[(b * SEQ + n * BSZ + j) * DM + h * HD + d] + pos[c];
    unsigned short hh, ll; split_bf16(val, hh, ll);
    AH[idx] = hh; AL[idx] = ll;
}

// ============= Tensor-core GEMM, pre-split operands (3-term bf16) ================
// C[M,N] = act(A@B + bias). A given as AH/AL [M][K] bf16; B as BTH/BTL [N][K] bf16.
// M%128==0, K%16==0. N tail guarded. 128x128 tile, BK=16, 256 thr (2x4 warps).
#define KS 24
__global__ void __launch_bounds__(256) hgemm3_kernel(
    const unsigned short* __restrict__ AH, const unsigned short* __restrict__ AL,
    const unsigned short* __restrict__ BTH, const unsigned short* __restrict__ BTL,
    const float* __restrict__ bias, float* __restrict__ C,
    int M, int N, int K, int act)
{
    __shared__ __align__(16) unsigned short sAH[2][128][KS];
    __shared__ __align__(16) unsigned short sAL[2][128][KS];
    __shared__ __align__(16) unsigned short sBH[2][128][KS];
    __shared__ __align__(16) unsigned short sBL[2][128][KS];

    const int tid  = threadIdx.x;
    const int lane = tid & 31;
    const int w    = tid >> 5;
    const int warp_m = (w & 1) * 64;
    const int warp_n = (w >> 1) * 32;
    const int row0 = blockIdx.y * 128;
    const int col0 = blockIdx.x * 128;
    const int g  = lane >> 2;
    const int t4 = lane & 3;

    // fill mapping: one uint4 (8 bf16) per thread per array per tile
    const int frow = tid >> 1;
    const int foff = (tid & 1) * 8;
    const bool bok = (col0 + frow) < N;
    const unsigned short* pAH = AH + (size_t)(row0 + frow) * K + foff;
    const unsigned short* pAL = AL + (size_t)(row0 + frow) * K + foff;
    const unsigned short* pBH = BTH + (size_t)(col0 + frow) * K + foff;
    const unsigned short* pBL = BTL + (size_t)(col0 + frow) * K + foff;

    float acc[4][4][4];
#pragma unroll
    for (int mi = 0; mi < 4; mi++)
#pragma unroll
        for (int ni = 0; ni < 4; ni++)
#pragma unroll
            for (int c = 0; c < 4; c++) acc[mi][ni][c] = 0.f;

    const int ntiles = K / 16;
    const uint4 z4 = make_uint4(0u, 0u, 0u, 0u);
    uint4 rah, ral, rbh, rbl;

    // prefetch tile 0
    rah = *(const uint4*)pAH;
    ral = *(const uint4*)pAL;
    rbh = bok ? *(const uint4*)pBH : z4;
    rbl = bok ? *(const uint4*)pBL : z4;
    *(uint4*)&sAH[0][frow][foff] = rah;
    *(uint4*)&sAL[0][frow][foff] = ral;
    *(uint4*)&sBH[0][frow][foff] = rbh;
    *(uint4*)&sBL[0][frow][foff] = rbl;
    __syncthreads();

    int buf = 0;
    for (int t = 0; t < ntiles; t++) {
        const bool more = (t + 1 < ntiles);
        if (more) {
            const int kt = (t + 1) * 16;
            rah = *(const uint4*)(pAH + kt);
            ral = *(const uint4*)(pAL + kt);
            rbh = bok ? *(const uint4*)(pBH + kt) : z4;
            rbl = bok ? *(const uint4*)(pBL + kt) : z4;
        }

        // fragments (conflict-free: word = 12r + t4, |group distance| >= 4)
        unsigned aH[4][4], aL[4][4], bH[4][2], bL[4][2];
#pragma unroll
        for (int mi = 0; mi < 4; mi++) {
            const int r = warp_m + mi * 16 + g;
            aH[mi][0] = *(const unsigned*)&sAH[buf][r    ][2*t4];
            aH[mi][1] = *(const unsigned*)&sAH[buf][r + 8][2*t4];
            aH[mi][2] = *(const unsigned*)&sAH[buf][r    ][2*t4 + 8];
            aH[mi][3] = *(const unsigned*)&sAH[buf][r + 8][2*t4 + 8];
            aL[mi][0] = *(const unsigned*)&sAL[buf][r    ][2*t4];
            aL[mi][1] = *(const unsigned*)&sAL[buf][r + 8][2*t4];
            aL[mi][2] = *(const unsigned*)&sAL[buf][r    ][2*t4 + 8];
            aL[mi][3] = *(const unsigned*)&sAL[buf][r + 8][2*t4 + 8];
        }
#pragma unroll
        for (int ni = 0; ni < 4; ni++) {
            const int n = warp_n + ni * 8 + g;
            bH[ni][0] = *(const unsigned*)&sBH[buf][n][2*t4];
            bH[ni][1] = *(const unsigned*)&sBH[buf][n][2*t4 + 8];
            bL[ni][0] = *(const unsigned*)&sBL[buf][n][2*t4];
            bL[ni][1] = *(const unsigned*)&sBL[buf][n][2*t4 + 8];
        }

#pragma unroll
        for (int mi = 0; mi < 4; mi++)
#pragma unroll
            for (int ni = 0; ni < 4; ni++) {
                mma_bf16(acc[mi][ni], aH[mi][0], aH[mi][1], aH[mi][2], aH[mi][3],
                         bH[ni][0], bH[ni][1]);
                mma_bf16(acc[mi][ni], aH[mi][0], aH[mi][1], aH[mi][2], aH[mi][3],
                         bL[ni][0], bL[ni][1]);
                mma_bf16(acc[mi][ni], aL[mi][0], aL[mi][1], aL[mi][2], aL[mi][3],
                         bH[ni][0], bH[ni][1]);
            }

        if (more) {
            const int nb = buf ^ 1;
            *(uint4*)&sAH[nb][frow][foff] = rah;
            *(uint4*)&sAL[nb][frow][foff] = ral;
            *(uint4*)&sBH[nb][frow][foff] = rbh;
            *(uint4*)&sBL[nb][frow][foff] = rbl;
            __syncthreads();
            buf = nb;
        }
    }

    // ---- epilogue ----
#pragma unroll
    for (int mi = 0; mi < 4; mi++) {
#pragma unroll
        for (int ni = 0; ni < 4; ni++) {
            const int row = row0 + warp_m + mi * 16 + g;
            const int col = col0 + warp_n + ni * 8 + 2 * t4;
            if (col + 1 < N) {
                float2 o0, o1;
                o0.x = acc[mi][ni][0] + bias[col];
                o0.y = acc[mi][ni][1] + bias[col + 1];
                o1.x = acc[mi][ni][2] + bias[col];
                o1.y = acc[mi][ni][3] + bias[col + 1];
                if (act == 1) {
                    o0.x = gelu_f(o0.x); o0.y = gelu_f(o0.y);
                    o1.x = gelu_f(o1.x); o1.y = gelu_f(o1.y);
                }
                *(float2*)&C[row * N + col]       = o0;
                *(float2*)&C[(row + 8) * N + col] = o1;
            } else if (col < N) {
                float v0 = acc[mi][ni][0] + bias[col];
                float v1 = acc[mi][ni][2] + bias[col];
                if (act == 1) { v0 = gelu_f(v0); v1 = gelu_f(v1); }
                C[row * N + col]       = v0;
                C[(row + 8) * N + col] = v1;
            }
        }
    }
}

// ------------- fp32 SGEMM — SELECTION-CRITICAL (Q, K) + tiny comp2 ----------------
__global__ void __launch_bounds__(256, 2) sgemm_kernel(
    const float* __restrict__ A, const float* __restrict__ B,
    const float* __restrict__ bias, float* __restrict__ C,
    int M, int N, int K, int act)
{
    __shared__ float As[2][16][132];
    __shared__ float Bs[2][16][128];

    const int tid  = threadIdx.x;
    const int row0 = blockIdx.y * 128;
    const int col0 = blockIdx.x * 128;
    const int trow = (tid >> 4) * 8;
    const int tcol = (tid & 15) * 8;

    const int a_row = tid >> 2;
    const int a_k   = (tid & 3) * 4;
    const int b_k   = tid >> 5;
    const int b_col = (tid & 31) * 4;
    const int gcol  = col0 + b_col;
    const bool bok  = (gcol < N);

    float acc[8][8];
#pragma unroll
    for (int i = 0; i < 8; i++)
#pragma unroll
        for (int j = 0; j < 8; j++) acc[i][j] = 0.f;

    float4 aReg[2], bReg[2];
    const int ntiles = K / 16;

#pragma unroll
    for (int i = 0; i < 2; i++) {
        aReg[i] = *(const float4*)&A[(row0 + a_row + i * 64) * K + a_k];
        bReg[i] = bok ? *(const float4*)&B[(b_k + i * 8) * N + gcol]
                      : make_float4(0.f, 0.f, 0.f, 0.f);
    }
#pragma unroll
    for (int i = 0; i < 2; i++) {
        As[0][a_k + 0][a_row + i * 64] = aReg[i].x;
        As[0][a_k + 1][a_row + i * 64] = aReg[i].y;
        As[0][a_k + 2][a_row + i * 64] = aReg[i].z;
        As[0][a_k + 3][a_row + i * 64] = aReg[i].w;
        *(float4*)&Bs[0][b_k + i * 8][b_col] = bReg[i];
    }
    __syncthreads();

    int buf = 0;
    for (int t = 0; t < ntiles; t++) {
        if (t + 1 < ntiles) {
            const int koff = (t + 1) * 16;
#pragma unroll
            for (int i = 0; i < 2; i++) {
                aReg[i] = *(const float4*)&A[(row0 + a_row + i * 64) * K + koff + a_k];
                bReg[i] = bok ? *(const float4*)&B[(koff + b_k + i * 8) * N + gcol]
                              : make_float4(0.f, 0.f, 0.f, 0.f);
            }
        }
#pragma unroll
        for (int k = 0; k < 16; k++) {
            float ar[8], br[8];
            *(float4*)&ar[0] = *(const float4*)&As[buf][k][trow];
            *(float4*)&ar[4] = *(const float4*)&As[buf][k][trow + 4];
            *(float4*)&br[0] = *(const float4*)&Bs[buf][k][tcol];
            *(float4*)&br[4] = *(const float4*)&Bs[buf][k][tcol + 4];
#pragma unroll
            for (int i = 0; i < 8; i++)
#pragma unroll
                for (int j = 0; j < 8; j++) acc[i][j] += ar[i] * br[j];
        }
        if (t + 1 < ntiles) {
            const int nb = buf ^ 1;
#pragma unroll
            for (int i = 0; i < 2; i++) {
                As[nb][a_k + 0][a_row + i * 64] = aReg[i].x;
                As[nb][a_k + 1][a_row + i * 64] = aReg[i].y;
                As[nb][a_k + 2][a_row + i * 64] = aReg[i].z;
                As[nb][a_k + 3][a_row + i * 64] = aReg[i].w;
                *(float4*)&Bs[nb][b_k + i * 8][b_col] = bReg[i];
            }
            __syncthreads();
            buf = nb;
        }
    }

#pragma unroll
    for (int i = 0; i < 8; i++) {
        const int r = row0 + trow + i;
#pragma unroll
        for (int j = 0; j < 8; j++) {
            const int c = col0 + tcol + j;
            if (c < N) {
                float val = acc[i][j] + bias[c];
                if (act == 1) val = gelu_f(val);
                C[r * N + c] = val;
            }
        }
    }
}

// ---------------- block-mean keys ------------------------------------------------
__global__ void kbar_kernel(const float* __restrict__ k, float* __restrict__ kb)
{
    int idx = blockIdx.x * 256 + threadIdx.x;
    int d = idx % HD;
    int n = (idx / HD) & 31;
    int h = (idx / (HD * 32)) & 31;
    int b = idx / (HD * 32 * 32);
    float s = 0.f;
#pragma unroll
    for (int j = 0; j < 32; j++)
        s += k[(b * SEQ + n * BSZ + j) * DM + h * HD + d];
    kb[idx] = s * 0.03125f;
}

// ---------------- top-k block selection -------------------------------------------
__global__ void __launch_bounds__(64) topk_kernel(
    const float* __restrict__ q, const float* __restrict__ kbar,
    unsigned* __restrict__ sel)
{
    __shared__ float Qs[64][84];
    __shared__ float Kb[32][84];
    const int q0 = blockIdx.x * 64;
    const int h = blockIdx.y, b = blockIdx.z;
    const int tid = threadIdx.x;

    for (int idx = tid; idx < 64 * 20; idx += 64) {
        int row = idx / 20, d4 = idx - row * 20;
        *(float4*)&Qs[row][d4 * 4] =
            *(const float4*)&q[(b * SEQ + q0 + row) * DM + h * HD + d4 * 4];
    }
    for (int idx = tid; idx < 32 * 20; idx += 64) {
        int row = idx / 20, d4 = idx - row * 20;
        *(float4*)&Kb[row][d4 * 4] =
            *(const float4*)&kbar[((b * NH + h) * NB + row) * HD + d4 * 4];
    }
    __syncthreads();

    float sc[32];
#pragma unroll
    for (int n = 0; n < 32; n++) {
        float s = 0.f;
        for (int d4 = 0; d4 < 20; d4++) {
            float4 qv = *(const float4*)&Qs[tid][d4 * 4];
            float4 kv = *(const float4*)&Kb[n][d4 * 4];
            s += qv.x * kv.x + qv.y * kv.y + qv.z * kv.z + qv.w * kv.w;
        }
        sc[n] = s;
    }
    unsigned mask = 0;
#pragma unroll
    for (int t = 0; t < KTOP; t++) {
        float best = -1e38f; int bi = 0;
#pragma unroll
        for (int n = 0; n < 32; n++) {
            if (!((mask >> n) & 1u) && sc[n] > best) { best = sc[n]; bi = n; }
        }
        mask |= (1u << bi);
    }
    sel[(b * NH + h) * SEQ + q0 + tid] = mask;
}

// ---------------- gates ------------------------------------------------------------
__global__ void __launch_bounds__(256) gates_kernel(
    const float* __restrict__ gh, const float* __restrict__ W2,
    const float* __restrict__ b2, float* __restrict__ gates)
{
    int gw = (blockIdx.x * 256 + threadIdx.x) >> 5;
    int lane = threadIdx.x & 31;
    if (gw >= NTOK * 3) return;
    int row = gw / 3, col = gw - row * 3;
    float s = 0.f;
    for (int i = lane; i < DM / 2; i += 32)
        s += gh[row * (DM / 2) + i] * W2[i * 3 + col];
#pragma unroll
    for (int o = 16; o > 0; o >>= 1) s += __shfl_down_sync(0xffffffffu, s, o);
    if (lane == 0)
        gates[row * 3 + col] = 1.f / (1.f + __expf(-(s + b2[col])));
}

// ---------------- fused attention: window + selected + compressed ----------------
__global__ void __launch_bounds__(256) attn_kernel(
    const float* __restrict__ q, const float* __restrict__ k, const float* __restrict__ v,
    const float* __restrict__ kc, const float* __restrict__ vc,
    const unsigned* __restrict__ sel, const float* __restrict__ gates,
    float* __restrict__ comb)
{
    __shared__ float Qs[32][84];
    __shared__ float Ks[32][84];
    __shared__ float Vs[32][84];
    __shared__ float Ssm[32][36];

    const int q0 = blockIdx.x * 32;
    const int h  = blockIdx.y;
    const int b  = blockIdx.z;
    const int tid = threadIdx.x;
    const int qi = tid >> 3;
    const int r  = tid & 7;
    const int d0 = r * 10;
    const int j0 = r * 4;

    for (int idx = tid; idx < 32 * 20; idx += 256) {
        int row = idx / 20, d4 = idx - row * 20;
        *(float4*)&Qs[row][d4 * 4] =
            *(const float4*)&q[(b * SEQ + q0 + row) * DM + h * HD + d4 * 4];
    }
    const unsigned msel = sel[(b * NH + h) * SEQ + q0 + qi];
    const int qrow = b * SEQ + q0 + qi;

    float mrun = -1e30f, lw = 0.f, ls = 0.f;
    float aw[10], asv[10];
#pragma unroll
    for (int i = 0; i < 10; i++) { aw[i] = 0.f; asv[i] = 0.f; }

    for (int n = 0; n < NB; n++) {
        __syncthreads();
        for (int idx = tid; idx < 32 * 20; idx += 256) {
            int row = idx / 20, d4 = idx - row * 20;
            int g = (b * SEQ + n * BSZ + row) * DM + h * HD + d4 * 4;
            *(float4*)&Ks[row][d4 * 4] = *(const float4*)&k[g];
            *(float4*)&Vs[row][d4 * 4] = *(const float4*)&v[g];
        }
        __syncthreads();

        float s0 = 0.f, s1 = 0.f, s2 = 0.f, s3 = 0.f;
#pragma unroll
        for (int d4 = 0; d4 < 20; d4++) {
            float4 qv = *(const float4*)&Qs[qi][d4 * 4];
            float4 k0 = *(const float4*)&Ks[j0 + 0][d4 * 4];
            float4 k1 = *(const float4*)&Ks[j0 + 1][d4 * 4];
            float4 k2 = *(const float4*)&Ks[j0 + 2][d4 * 4];
            float4 k3 = *(const float4*)&Ks[j0 + 3][d4 * 4];
            s0 += qv.x * k0.x + qv.y * k0.y + qv.z * k0.z + qv.w * k0.w;
            s1 += qv.x * k1.x + qv.y * k1.y + qv.z * k1.z + qv.w * k1.w;
            s2 += qv.x * k2.x + qv.y * k2.y + qv.z * k2.z + qv.w * k2.w;
            s3 += qv.x * k3.x + qv.y * k3.y + qv.z * k3.z + qv.w * k3.w;
        }
        s0 *= ATT_SCALE; s1 *= ATT_SCALE; s2 *= ATT_SCALE; s3 *= ATT_SCALE;
        *(float4*)&Ssm[qi][j0] = make_float4(s0, s1, s2, s3);
        __syncwarp();
        float mb = -1e30f;
#pragma unroll
        for (int j4 = 0; j4 < 8; j4++) {
            float4 t4 = *(const float4*)&Ssm[qi][j4 * 4];
            mb = fmaxf(mb, fmaxf(fmaxf(t4.x, t4.y), fmaxf(t4.z, t4.w)));
        }
        float mnew = fmaxf(mrun, mb);
        float alpha = __expf(mrun - mnew);
        __syncwarp();
        *(float4*)&Ssm[qi][j0] = make_float4(__expf(s0 - mnew), __expf(s1 - mnew),
                                             __expf(s2 - mnew), __expf(s3 - mnew));
        __syncwarp();

        float ps = 0.f;
        const float fsel = ((msel >> n) & 1u) ? 1.f : 0.f;
        lw *= alpha; ls *= alpha;
#pragma unroll
        for (int i = 0; i < 10; i++) { aw[i] *= alpha; asv[i] *= alpha; }
#pragma unroll
        for (int j4 = 0; j4 < 8; j4++) {
            float4 p4 = *(const float4*)&Ssm[qi][j4 * 4];
            ps += p4.x + p4.y + p4.z + p4.w;
            float pj[4] = {p4.x, p4.y, p4.z, p4.w};
#pragma unroll
            for (int jj = 0; jj < 4; jj++) {
                const float p  = pj[jj];
                const float pf = p * fsel;
                const int   j  = j4 * 4 + jj;
#pragma unroll
                for (int i2 = 0; i2 < 5; i2++) {
                    float2 v2 = *(const float2*)&Vs[j][d0 + 2 * i2];
                    aw[2 * i2]      += p  * v2.x;
                    aw[2 * i2 + 1]  += p  * v2.y;
                    asv[2 * i2]     += pf * v2.x;
                    asv[2 * i2 + 1] += pf * v2.y;
                }
            }
        }
        lw += ps;
        ls += fsel * ps;
        mrun = mnew;
    }

    __syncthreads();
    for (int idx = tid; idx < 32 * 20; idx += 256) {
        int row = idx / 20, d4 = idx - row * 20;
        int g = ((b * NH + h) * NB + row) * HD + d4 * 4;
        *(float4*)&Ks[row][d4 * 4] = *(const float4*)&kc[g];
        *(float4*)&Vs[row][d4 * 4] = *(const float4*)&vc[g];
    }
    __syncthreads();
    float c0 = 0.f, c1 = 0.f, c2 = 0.f, c3 = 0.f;
#pragma unroll
    for (int d4 = 0; d4 < 20; d4++) {
        float4 qv = *(const float4*)&Qs[qi][d4 * 4];
        float4 k0 = *(const float4*)&Ks[j0 + 0][d4 * 4];
        float4 k1 = *(const float4*)&Ks[j0 + 1][d4 * 4];
        float4 k2 = *(const float4*)&Ks[j0 + 2][d4 * 4];
        float4 k3 = *(const float4*)&Ks[j0 + 3][d4 * 4];
        c0 += qv.x * k0.x + qv.y * k0.y + qv.z * k0.z + qv.w * k0.w;
        c1 += qv.x * k1.x + qv.y * k1.y + qv.z * k1.z + qv.w * k1.w;
        c2 += qv.x * k2.x + qv.y * k2.y + qv.z * k2.z + qv.w * k2.w;
        c3 += qv.x * k3.x + qv.y * k3.y + qv.z * k3.z + qv.w * k3.w;
    }
    c0 *= ATT_SCALE; c1 *= ATT_SCALE; c2 *= ATT_SCALE; c3 *= ATT_SCALE;
    *(float4*)&Ssm[qi][j0] = make_float4(c0, c1, c2, c3);
    __syncwarp();
    float mc = -1e30f;
#pragma unroll
    for (int j4 = 0; j4 < 8; j4++) {
        float4 t4 = *(const float4*)&Ssm[qi][j4 * 4];
        mc = fmaxf(mc, fmaxf(fmaxf(t4.x, t4.y), fmaxf(t4.z, t4.w)));
    }
    __syncwarp();
    *(float4*)&Ssm[qi][j0] = make_float4(__expf(c0 - mc), __expf(c1 - mc),
                                         __expf(c2 - mc), __expf(c3 - mc));
    __syncwarp();
    float lc = 0.f;
    float ac[10];
#pragma unroll
    for (int i = 0; i < 10; i++) ac[i] = 0.f;
#pragma unroll
    for (int j4 = 0; j4 < 8; j4++) {
        float4 p4 = *(const float4*)&Ssm[qi][j4 * 4];
        lc += p4.x + p4.y + p4.z + p4.w;
        float pj[4] = {p4.x, p4.y, p4.z, p4.w};
#pragma unroll
        for (int jj = 0; jj < 4; jj++) {
            const float p = pj[jj];
            const int   j = j4 * 4 + jj;
#pragma unroll
            for (int i2 = 0; i2 < 5; i2++) {
                float2 v2 = *(const float2*)&Vs[j][d0 + 2 * i2];
                ac[2 * i2]     += p * v2.x;
                ac[2 * i2 + 1] += p * v2.y;
            }
        }
    }

    const float gc = gates[qrow * 3 + 0];
    const float gs = gates[qrow * 3 + 1];
    const float gw = gates[qrow * 3 + 2];
    const float ic  = gc / lc;
    const float isf = gs / ls;
    const float iwf = gw / lw;
#pragma unroll
    for (int i = 0; i < 10; i++)
        comb[qrow * DM + h * HD + d0 + i] = ic * ac[i] + isf * asv[i] + iwf * aw[i];
}

// ---------------------------------- launch ---------------------------------------
static inline int ceil_div(int a, int b) { return (a + b - 1) / b; }

extern "C" void kernel_launch(void* const* d_in, const int* in_sizes, int n_in,
                              void* d_out, int out_size)
{
    const float* hs       = (const float*)d_in[0];
    const float* Wq       = (const float*)d_in[1];
    const float* bq       = (const float*)d_in[2];
    const float* Wk       = (const float*)d_in[3];
    const float* bk       = (const float*)d_in[4];
    const float* Wv       = (const float*)d_in[5];
    const float* bv       = (const float*)d_in[6];
    const float* Wo       = (const float*)d_in[7];
    const float* bo       = (const float*)d_in[8];
    const float* comp_pos = (const float*)d_in[9];
    const float* comp_W1  = (const float*)d_in[10];
    const float* comp_b1  = (const float*)d_in[11];
    const float* comp_W2  = (const float*)d_in[12];
    const float* comp_b2  = (const float*)d_in[13];
    const float* gate_W1  = (const float*)d_in[14];
    const float* gate_b1  = (const float*)d_in[15];
    const float* gate_W2  = (const float*)d_in[16];
    const float* gate_b2  = (const float*)d_in[17];
    float* out = (float*)d_out;

    float *q, *k, *v, *comb, *gh, *gates, *kbar, *H1, *kc, *vc;
    unsigned* selp;
    unsigned short *hsH, *hsL, *cbH, *cbL, *acH, *acL;
    unsigned short *WvTH, *WvTL, *WoTH, *WoTL, *gW1TH, *gW1TL, *cW1TH, *cW1TL;
    cudaGetSymbolAddress((void**)&q,     g_q);
    cudaGetSymbolAddress((void**)&k,     g_k);
    cudaGetSymbolAddress((void**)&v,     g_v);
    cudaGetSymbolAddress((void**)&comb,  g_comb);
    cudaGetSymbolAddress((void**)&gh,    g_gh);
    cudaGetSymbolAddress((void**)&gates, g_gates);
    cudaGetSymbolAddress((void**)&kbar,  g_kbar);
    cudaGetSymbolAddress((void**)&H1,    g_H1);
    cudaGetSymbolAddress((void**)&kc,    g_kc);
    cudaGetSymbolAddress((void**)&vc,    g_vc);
    cudaGetSymbolAddress((void**)&selp,  g_sel);
    cudaGetSymbolAddress((void**)&hsH,   g_hsH);
    cudaGetSymbolAddress((void**)&hsL,   g_hsL);
    cudaGetSymbolAddress((void**)&cbH,   g_cbH);
    cudaGetSymbolAddress((void**)&cbL,   g_cbL);
    cudaGetSymbolAddress((void**)&acH,   g_acH);
    cudaGetSymbolAddress((void**)&acL,   g_acL);
    cudaGetSymbolAddress((void**)&WvTH,  g_WvTH);
    cudaGetSymbolAddress((void**)&WvTL,  g_WvTL);
    cudaGetSymbolAddress((void**)&WoTH,  g_WoTH);
    cudaGetSymbolAddress((void**)&WoTL,  g_WoTL);
    cudaGetSymbolAddress((void**)&gW1TH, g_gW1TH);
    cudaGetSymbolAddress((void**)&gW1TL, g_gW1TL);
    cudaGetSymbolAddress((void**)&cW1TH, g_cW1TH);
    cudaGetSymbolAddress((void**)&cW1TL, g_cW1TL);

    // ---- pre-split/transposed operands (bandwidth-bound, ~100us total) ----
    {
        dim3 thr(32, 8);
        split_tr_kernel<<<dim3(DM / 32, DM / 32), thr>>>(Wv, WvTH, WvTL, DM, DM);
        split_tr_kernel<<<dim3(DM / 32, DM / 32), thr>>>(Wo, WoTH, WoTL, DM, DM);
        split_tr_kernel<<<dim3((DM/2) / 32, DM / 32), thr>>>(gate_W1, gW1TH, gW1TL, DM, DM / 2);
        split_tr_kernel<<<dim3(320 / 32, DM / 32), thr>>>(comp_W1, cW1TH, cW1TL, DM, 320);
        split_vec_kernel<<<(NTOK * DM / 4 + 255) / 256, 256>>>(hs, hsH, hsL, NTOK * DM / 4);
    }

    // Q, K projections: fp32 (selection-critical)
    {
        dim3 grid(DM / 128, NTOK / 128);
        sgemm_kernel<<<grid, 256>>>(hs, Wq, bq, q, NTOK, DM, DM, 0);
        sgemm_kernel<<<grid, 256>>>(hs, Wk, bk, k, NTOK, DM, DM, 0);
    }
    // V projection: tensor cores
    hgemm3_kernel<<<dim3(DM / 128, NTOK / 128), 256>>>(hsH, hsL, WvTH, WvTL, bv, v,
                                                       NTOK, DM, DM, 0);
    // gate hidden + gates
    hgemm3_kernel<<<dim3((DM/2) / 128, NTOK / 128), 256>>>(hsH, hsL, gW1TH, gW1TL,
                                                           gate_b1, gh, NTOK, DM / 2, DM, 1);
    gates_kernel<<<ceil_div(NTOK * 3 * 32, 256), 256>>>(gh, gate_W2, gate_b2, gates);

    // block-mean keys (fp32 k -> selection exact)
    kbar_kernel<<<(BATCH * NH * NB * HD) / 256, 256>>>(k, kbar);

    // compression MLP for K
    {
        gather_comp_split<<<(NCOMP * DM) / 256, 256>>>(k, comp_pos, acH, acL);
        hgemm3_kernel<<<dim3(ceil_div(320, 128), NCOMP / 128), 256>>>(
            acH, acL, cW1TH, cW1TL, comp_b1, H1, NCOMP, 320, DM, 1);
        sgemm_kernel<<<dim3(1, NCOMP / 128), 256>>>(H1, comp_W2, comp_b2, kc,
                                                    NCOMP, HD, 320, 0);
    }
    // compression MLP for V
    {
        gather_comp_split<<<(NCOMP * DM) / 256, 256>>>(v, comp_pos, acH, acL);
        hgemm3_kernel<<<dim3(ceil_div(320, 128), NCOMP / 128), 256>>>(
            acH, acL, cW1TH, cW1TL, comp_b1, H1, NCOMP, 320, DM, 1);
        sgemm_kernel<<<dim3(1, NCOMP / 128), 256>>>(H1, comp_W2, comp_b2, vc,
                                                    NCOMP, HD, 320, 0);
    }

    // top-k block selection (fp32 q, kbar)
    topk_kernel<<<dim3(SEQ / 64, NH, BATCH), 64>>>(q, kbar, selp);

    // fused attention (window + selected + compressed + gating)
    attn_kernel<<<dim3(SEQ / 32, NH, BATCH), 256>>>(q, k, v, kc, vc, selp, gates, comb);

    // output projection: split comb, then tensor cores
    split_vec_kernel<<<(NTOK * DM / 4 + 255) / 256, 256>>>(comb, cbH, cbL, NTOK * DM / 4);
    hgemm3_kernel<<<dim3(DM / 128, NTOK / 128), 256>>>(cbH, cbL, WoTH, WoTL, bo, out,
                                                       NTOK, DM, DM, 0);
}